// round 10
// baseline (speedup 1.0000x reference)
#include <cuda_runtime.h>

// Chamfer distance loss on (2,8,4096,3) fp32 clouds.
// Shared distance matrix (268M pairs): each pair updates the pred-side row-min
// and the targ-side col-min.  Min combining = atomicMax on inverted keys
// key = ~bits(max(d2,0)); identity 0 -> statically zero-init buffer; the
// reduce kernel re-zeroes slots after reading (stream-ordered for replay).
//
// Round-10: TC=1024 (chunk overhead halved again) + main kernel placed at
// launch position 4 (ncu empirically profiles the 4th launch -> finally get
// the hot kernel's roofline).

#define NPTS    4096
#define NBATCH  16
#define THREADS 256
#define GRID    296                     // 2 blocks/SM x 148
#define TC      1024                    // targets per chunk
#define NCHUNK  (NBATCH * 32 * 4)       // 2048 chunks (32 qstrips x 4 tchunks)
#define NQTOT   (2 * NBATCH * NPTS)     // 131072
#define BIGF    3.4e38f

#define P2_BLOCKS 128
#define P2_THREADS 256

typedef unsigned long long ull;

__device__ unsigned g_key[NQTOT];       // zero-init; [0:65536)=pred rows, rest=targ cols
__device__ float    g_sum;
__device__ unsigned g_done;
__device__ unsigned g_tick;

__device__ __forceinline__ ull dupf(float v) {
    ull r; asm("mov.b64 %0, {%1, %1};" : "=l"(r) : "f"(v)); return r;
}
__device__ __forceinline__ ull pk(float lo, float hi) {
    ull r; asm("mov.b64 %0, {%1, %2};" : "=l"(r) : "f"(lo), "f"(hi)); return r;
}
__device__ __forceinline__ unsigned mkkey(float d2) {
    return ~__float_as_uint(fmaxf(d2, 0.0f));
}

// ---- launch 1: reset accumulators ----
__global__ void cd_reset_kernel() { g_sum = 0.0f; g_done = 0u; }
// ---- launches 2,3: alignment pads so main is the 4th launch ----
__global__ void cd_pad1_kernel() { g_tick = 1u; }
__global__ void cd_pad2_kernel() { g_tick = 2u; }

// ---- launch 4: pairwise mins (profiled by ncu) ----
__global__ void __launch_bounds__(THREADS, 2)
cd_main_kernel(const float* __restrict__ pred, const float* __restrict__ targ) {
    __shared__ __align__(16) float4 sA[TC / 2];   // (y0_t0,y0_t1,y1_t0,y1_t1)
    __shared__ __align__(16) float4 sB[TC / 2];   // (y2_t0,y2_t1, h_t0, h_t1)
    __shared__ unsigned scol[TC];

    const int tid = threadIdx.x;
    const int tx  = tid & 15;
    const int ty  = tid >> 4;
    const int bid = blockIdx.x;

#pragma unroll
    for (int z = 0; z < 4; z++) scol[tid + z * 256] = 0u;   // identity

    const int c0 = (int)(((long long)bid       * NCHUNK) / GRID);
    const int c1 = (int)(((long long)(bid + 1) * NCHUNK) / GRID);

    ull  m0[8], m1[8], m2[8], x2d[8];   // duplicated-lane query state
    float ralo[8], rahi[8];             // row-min accumulators
    int cur_strip = -1, cur_qbase = 0;

    for (int cid = c0; cid < c1; cid++) {
        const int b  = cid >> 7;        // 128 chunks per batch (32 qs x 4 tc)
        const int rr = cid & 127;
        const int qs = rr >> 2;
        const int tc = rr & 3;

        // ---- query strip management: flush 8 row mins, load 8 new queries ----
        const int strip = (b << 5) | qs;
        if (strip != cur_strip) {
            if (cur_strip >= 0) {
#pragma unroll
                for (int i = 0; i < 8; i++)
                    atomicMax(&g_key[cur_qbase + (ty << 3) + i],
                              mkkey(fminf(ralo[i], rahi[i])));
            }
            cur_strip = strip;
            cur_qbase = (b << 12) + (qs << 7);
            // 8 points = 24 floats = 6 x float4 (96B, 16B-aligned)
            const float4* __restrict__ qv =
                (const float4*)(pred + (size_t)(cur_qbase + (ty << 3)) * 3);
            float4 f[6];
#pragma unroll
            for (int i = 0; i < 6; i++) f[i] = qv[i];
            const float* q = (const float*)f;
#pragma unroll
            for (int i = 0; i < 8; i++) {
                const float x0 = q[i * 3 + 0];
                const float x1 = q[i * 3 + 1];
                const float x2 = q[i * 3 + 2];
                m0[i]  = dupf(-2.0f * x0);
                m1[i]  = dupf(-2.0f * x1);
                m2[i]  = dupf(-2.0f * x2);
                x2d[i] = dupf(x0 * x0 + x1 * x1 + x2 * x2);
                ralo[i] = BIGF; rahi[i] = BIGF;
            }
        }

        // ---- fill target tile: 256 threads x 4 targets (3 x LDG.128 each) ----
        {
            const float4* __restrict__ bv = (const float4*)
                (targ + (size_t)((b << 12) + (tc << 10) + tid * 4) * 3);
            const float4 f0 = bv[0], f1 = bv[1], f2 = bv[2];
            // targets t0=(f0.x,f0.y,f0.z) t1=(f0.w,f1.x,f1.y)
            //         t2=(f1.z,f1.w,f2.x) t3=(f2.y,f2.z,f2.w)
            sA[2 * tid]     = make_float4(f0.x, f0.w, f0.y, f1.x);
            sB[2 * tid]     = make_float4(f0.z, f1.y,
                                          f0.x * f0.x + f0.y * f0.y + f0.z * f0.z,
                                          f0.w * f0.w + f1.x * f1.x + f1.y * f1.y);
            sA[2 * tid + 1] = make_float4(f1.z, f2.y, f1.w, f2.z);
            sB[2 * tid + 1] = make_float4(f2.x, f2.w,
                                          f1.z * f1.z + f1.w * f1.w + f2.x * f2.x,
                                          f2.y * f2.y + f2.z * f2.z + f2.w * f2.w);
        }
        __syncthreads();    // A: tile + scol(identity) visible

        // ---- main: 32 target-pairs x 8 queries = 512 pairs/thread ----
#pragma unroll
        for (int k = 0; k < 32; k++) {
            const int pw = tx + (k << 4);
            const float4 ua = sA[pw];     // LDS.128
            const float4 ub = sB[pw];     // LDS.128
            const ull y0p = pk(ua.x, ua.y);
            const ull y1p = pk(ua.z, ua.w);
            const ull y2p = pk(ub.x, ub.y);
            const ull hp  = pk(ub.z, ub.w);
            float clo = BIGF, chi = BIGF;
#pragma unroll
            for (int q = 0; q < 8; q++) {
                ull s, w;
                asm("add.rn.f32x2 %0, %1, %2;"     : "=l"(s) : "l"(x2d[q]), "l"(hp));
                asm("fma.rn.f32x2 %0, %1, %2, %3;" : "=l"(w) : "l"(m2[q]), "l"(y2p), "l"(s));
                asm("fma.rn.f32x2 %0, %1, %2, %3;" : "=l"(w) : "l"(m1[q]), "l"(y1p), "l"(w));
                asm("fma.rn.f32x2 %0, %1, %2, %3;" : "=l"(w) : "l"(m0[q]), "l"(y0p), "l"(w));
                float wl, wh;
                asm("mov.b64 {%0, %1}, %2;" : "=f"(wl), "=f"(wh) : "l"(w));
                ralo[q] = fminf(ralo[q], wl);
                rahi[q] = fminf(rahi[q], wh);
                clo = fminf(clo, wl);
                chi = fminf(chi, wh);
            }
            // in-loop, return-less col merges
            const int w2 = (tx << 1) + (k << 5);
            atomicMax(&scol[w2],     mkkey(clo));
            atomicMax(&scol[w2 + 1], mkkey(chi));
        }
        __syncthreads();    // B: scol complete; tile reads done

        // ---- four global return-less atomicMax per thread; reset own slots ----
        const int gb = (NBATCH * NPTS) + (b << 12) + (tc << 10);
#pragma unroll
        for (int z = 0; z < 4; z++) {
            atomicMax(&g_key[gb + tid + z * 256], scol[tid + z * 256]);
            scol[tid + z * 256] = 0u;
        }
    }

    // final row flush
    if (cur_strip >= 0) {
#pragma unroll
        for (int i = 0; i < 8; i++)
            atomicMax(&g_key[cur_qbase + (ty << 3) + i],
                      mkkey(fminf(ralo[i], rahi[i])));
    }
}

// ---- launch 5: sqrt + mean; re-zeroes g_key for the next replay ----
__global__ void __launch_bounds__(P2_THREADS)
cd_reduce_kernel(float* __restrict__ out) {
    __shared__ float swsum[P2_THREADS / 32];
    const int tid = threadIdx.x;
    const int i = blockIdx.x * P2_THREADS + tid;     // 32768 threads, 1 uint4 each
    uint4* kp = reinterpret_cast<uint4*>(g_key);
    const uint4 kv = kp[i];
    float lsum = sqrtf(__uint_as_float(~kv.x)) + sqrtf(__uint_as_float(~kv.y))
               + sqrtf(__uint_as_float(~kv.z)) + sqrtf(__uint_as_float(~kv.w));
    kp[i] = make_uint4(0u, 0u, 0u, 0u);              // identity for next call
#pragma unroll
    for (int off = 16; off > 0; off >>= 1)
        lsum += __shfl_down_sync(0xFFFFFFFFu, lsum, off);
    const int lane = tid & 31;
    const int wid  = tid >> 5;
    if (lane == 0) swsum[wid] = lsum;
    __syncthreads();
    if (wid == 0) {
        float v = (lane < P2_THREADS / 32) ? swsum[lane] : 0.0f;
#pragma unroll
        for (int off = (P2_THREADS / 32) / 2; off > 0; off >>= 1)
            v += __shfl_down_sync(0xFFFFFFFFu, v, off);
        if (lane == 0) {
            atomicAdd(&g_sum, v);
            __threadfence();
            const unsigned rdone = atomicAdd(&g_done, 1u);
            if (rdone == P2_BLOCKS - 1)
                out[0] = atomicAdd(&g_sum, 0.0f) * (1.0f / (float)(NBATCH * NPTS));
        }
    }
}

extern "C" void kernel_launch(void* const* d_in, const int* in_sizes, int n_in,
                              void* d_out, int out_size) {
    const float* pred = (const float*)d_in[0];
    const float* targ = (const float*)d_in[1];
    float* out = (float*)d_out;
    cd_reset_kernel<<<1, 1>>>();                      // 1
    cd_pad1_kernel<<<1, 1>>>();                       // 2
    cd_pad2_kernel<<<1, 1>>>();                       // 3
    cd_main_kernel<<<GRID, THREADS>>>(pred, targ);    // 4  <- ncu profiles this
    cd_reduce_kernel<<<P2_BLOCKS, P2_THREADS>>>(out); // 5
}

// round 12
// speedup vs baseline: 1.0004x; 1.0004x over previous
#include <cuda_runtime.h>

// Chamfer distance loss on (2,8,4096,3) fp32 clouds.
// Shared distance matrix (268M pairs): each pair updates the pred-side row-min
// and the targ-side col-min.  Min combining = atomicMax on inverted keys
// key = ~bits(max(d2,0)); identity 0 -> statically zero-init buffer; the
// reduce kernel re-zeroes slots after reading (stream-ordered for replay).
//
// Round-12 = Round-11 resubmitted (prior bench was a transient container
// failure; kernel has no spin/wait constructs that could hang):
// TC=512 (R9 best), col-min accumulators split into two independent chains
// (halved FMNMX dependency depth in the k-body), main kernel at launch
// position 4 for ncu visibility.

#define NPTS    4096
#define NBATCH  16
#define THREADS 256
#define GRID    296                     // 2 blocks/SM x 148
#define TC      512                     // targets per chunk
#define NCHUNK  (NBATCH * 32 * 8)       // 4096 chunks (32 qstrips x 8 tchunks)
#define NQTOT   (2 * NBATCH * NPTS)     // 131072
#define BIGF    3.4e38f

#define P2_BLOCKS 128
#define P2_THREADS 256

typedef unsigned long long ull;

__device__ unsigned g_key[NQTOT];       // zero-init; [0:65536)=pred rows, rest=targ cols
__device__ float    g_sum;
__device__ unsigned g_done;
__device__ unsigned g_tick;

__device__ __forceinline__ ull dupf(float v) {
    ull r; asm("mov.b64 %0, {%1, %1};" : "=l"(r) : "f"(v)); return r;
}
__device__ __forceinline__ ull pk(float lo, float hi) {
    ull r; asm("mov.b64 %0, {%1, %2};" : "=l"(r) : "f"(lo), "f"(hi)); return r;
}
__device__ __forceinline__ unsigned mkkey(float d2) {
    return ~__float_as_uint(fmaxf(d2, 0.0f));
}

// ---- launch 1: reset accumulators ----
__global__ void cd_reset_kernel() { g_sum = 0.0f; g_done = 0u; }
// ---- launches 2,3: alignment pads so main is the 4th launch (ncu target) ----
__global__ void cd_pad1_kernel() { g_tick = 1u; }
__global__ void cd_pad2_kernel() { g_tick = 2u; }

// ---- launch 4: pairwise mins (profiled by ncu) ----
__global__ void __launch_bounds__(THREADS, 2)
cd_main_kernel(const float* __restrict__ pred, const float* __restrict__ targ) {
    __shared__ __align__(16) float4 sA[TC / 2];   // (y0_t0,y0_t1,y1_t0,y1_t1)
    __shared__ __align__(16) float4 sB[TC / 2];   // (y2_t0,y2_t1, h_t0, h_t1)
    __shared__ unsigned scol[TC];

    const int tid = threadIdx.x;
    const int tx  = tid & 15;
    const int ty  = tid >> 4;
    const int bid = blockIdx.x;

    scol[tid] = 0u;                     // identity (both halves)
    scol[tid + 256] = 0u;

    const int c0 = (int)(((long long)bid       * NCHUNK) / GRID);
    const int c1 = (int)(((long long)(bid + 1) * NCHUNK) / GRID);

    ull  m0[8], m1[8], m2[8], x2d[8];   // duplicated-lane query state
    float ralo[8], rahi[8];             // row-min accumulators
    int cur_strip = -1, cur_qbase = 0;

    for (int cid = c0; cid < c1; cid++) {
        const int b  = cid >> 8;        // 256 chunks per batch (32 qs x 8 tc)
        const int rr = cid & 255;
        const int qs = rr >> 3;
        const int tc = rr & 7;

        // ---- query strip management: flush 8 row mins, load 8 new queries ----
        const int strip = (b << 5) | qs;
        if (strip != cur_strip) {
            if (cur_strip >= 0) {
#pragma unroll
                for (int i = 0; i < 8; i++)
                    atomicMax(&g_key[cur_qbase + (ty << 3) + i],
                              mkkey(fminf(ralo[i], rahi[i])));
            }
            cur_strip = strip;
            cur_qbase = (b << 12) + (qs << 7);
            // 8 points = 24 floats = 6 x float4 (96B, 16B-aligned)
            const float4* __restrict__ qv =
                (const float4*)(pred + (size_t)(cur_qbase + (ty << 3)) * 3);
            float4 f[6];
#pragma unroll
            for (int i = 0; i < 6; i++) f[i] = qv[i];
            const float* q = (const float*)f;
#pragma unroll
            for (int i = 0; i < 8; i++) {
                const float x0 = q[i * 3 + 0];
                const float x1 = q[i * 3 + 1];
                const float x2 = q[i * 3 + 2];
                m0[i]  = dupf(-2.0f * x0);
                m1[i]  = dupf(-2.0f * x1);
                m2[i]  = dupf(-2.0f * x2);
                x2d[i] = dupf(x0 * x0 + x1 * x1 + x2 * x2);
                ralo[i] = BIGF; rahi[i] = BIGF;
            }
        }

        // ---- fill target tile: 256 threads x 2 targets, interleaved float4 ----
        {
            const float* __restrict__ bp =
                targ + (size_t)((b << 12) + (tc << 9) + tid * 2) * 3;
            const float a0 = bp[0], a1 = bp[1], a2 = bp[2];
            const float b0 = bp[3], b1 = bp[4], b2 = bp[5];
            sA[tid] = make_float4(a0, b0, a1, b1);
            sB[tid] = make_float4(a2, b2,
                                  a0 * a0 + a1 * a1 + a2 * a2,
                                  b0 * b0 + b1 * b1 + b2 * b2);
        }
        __syncthreads();    // A: tile + scol(identity) visible

        // ---- main: 16 target-pairs x 8 queries = 256 pairs/thread ----
#pragma unroll
        for (int k = 0; k < 16; k++) {
            const int pw = tx + (k << 4);
            const float4 ua = sA[pw];     // LDS.128
            const float4 ub = sB[pw];     // LDS.128
            const ull y0p = pk(ua.x, ua.y);
            const ull y1p = pk(ua.z, ua.w);
            const ull y2p = pk(ub.x, ub.y);
            const ull hp  = pk(ub.z, ub.w);
            // two independent col-min chains (halved dependency depth)
            float cloA = BIGF, chiA = BIGF, cloB = BIGF, chiB = BIGF;
#pragma unroll
            for (int q = 0; q < 8; q++) {
                ull s, w;
                asm("add.rn.f32x2 %0, %1, %2;"     : "=l"(s) : "l"(x2d[q]), "l"(hp));
                asm("fma.rn.f32x2 %0, %1, %2, %3;" : "=l"(w) : "l"(m2[q]), "l"(y2p), "l"(s));
                asm("fma.rn.f32x2 %0, %1, %2, %3;" : "=l"(w) : "l"(m1[q]), "l"(y1p), "l"(w));
                asm("fma.rn.f32x2 %0, %1, %2, %3;" : "=l"(w) : "l"(m0[q]), "l"(y0p), "l"(w));
                float wl, wh;
                asm("mov.b64 {%0, %1}, %2;" : "=f"(wl), "=f"(wh) : "l"(w));
                ralo[q] = fminf(ralo[q], wl);
                rahi[q] = fminf(rahi[q], wh);
                if (q & 4) { cloB = fminf(cloB, wl); chiB = fminf(chiB, wh); }
                else       { cloA = fminf(cloA, wl); chiA = fminf(chiA, wh); }
            }
            // merge the two chains + in-loop return-less col atomics
            const int w2 = (tx << 1) + (k << 5);
            atomicMax(&scol[w2],     mkkey(fminf(cloA, cloB)));
            atomicMax(&scol[w2 + 1], mkkey(fminf(chiA, chiB)));
        }
        __syncthreads();    // B: scol complete; tile reads done

        // ---- two global return-less atomicMax per thread; reset own slots ----
        const int gb = (NBATCH * NPTS) + (b << 12) + (tc << 9);
        atomicMax(&g_key[gb + tid],       scol[tid]);
        atomicMax(&g_key[gb + tid + 256], scol[tid + 256]);
        scol[tid] = 0u;
        scol[tid + 256] = 0u;
    }

    // final row flush
    if (cur_strip >= 0) {
#pragma unroll
        for (int i = 0; i < 8; i++)
            atomicMax(&g_key[cur_qbase + (ty << 3) + i],
                      mkkey(fminf(ralo[i], rahi[i])));
    }
}

// ---- launch 5: sqrt + mean; re-zeroes g_key for the next replay ----
__global__ void __launch_bounds__(P2_THREADS)
cd_reduce_kernel(float* __restrict__ out) {
    __shared__ float swsum[P2_THREADS / 32];
    const int tid = threadIdx.x;
    const int i = blockIdx.x * P2_THREADS + tid;     // 32768 threads, 1 uint4 each
    uint4* kp = reinterpret_cast<uint4*>(g_key);
    const uint4 kv = kp[i];
    float lsum = sqrtf(__uint_as_float(~kv.x)) + sqrtf(__uint_as_float(~kv.y))
               + sqrtf(__uint_as_float(~kv.z)) + sqrtf(__uint_as_float(~kv.w));
    kp[i] = make_uint4(0u, 0u, 0u, 0u);              // identity for next call
#pragma unroll
    for (int off = 16; off > 0; off >>= 1)
        lsum += __shfl_down_sync(0xFFFFFFFFu, lsum, off);
    const int lane = tid & 31;
    const int wid  = tid >> 5;
    if (lane == 0) swsum[wid] = lsum;
    __syncthreads();
    if (wid == 0) {
        float v = (lane < P2_THREADS / 32) ? swsum[lane] : 0.0f;
#pragma unroll
        for (int off = (P2_THREADS / 32) / 2; off > 0; off >>= 1)
            v += __shfl_down_sync(0xFFFFFFFFu, v, off);
        if (lane == 0) {
            atomicAdd(&g_sum, v);
            __threadfence();
            const unsigned rdone = atomicAdd(&g_done, 1u);
            if (rdone == P2_BLOCKS - 1)
                out[0] = atomicAdd(&g_sum, 0.0f) * (1.0f / (float)(NBATCH * NPTS));
        }
    }
}

extern "C" void kernel_launch(void* const* d_in, const int* in_sizes, int n_in,
                              void* d_out, int out_size) {
    const float* pred = (const float*)d_in[0];
    const float* targ = (const float*)d_in[1];
    float* out = (float*)d_out;
    cd_reset_kernel<<<1, 1>>>();                      // 1
    cd_pad1_kernel<<<1, 1>>>();                       // 2
    cd_pad2_kernel<<<1, 1>>>();                       // 3
    cd_main_kernel<<<GRID, THREADS>>>(pred, targ);    // 4  <- ncu profiles this
    cd_reduce_kernel<<<P2_BLOCKS, P2_THREADS>>>(out); // 5
}

// round 13
// speedup vs baseline: 1.0519x; 1.0515x over previous
#include <cuda_runtime.h>

// Chamfer distance loss on (2,8,4096,3) fp32 clouds.
// Shared distance matrix (268M pairs): each pair updates the pred-side row-min
// and the targ-side col-min.  Min combining = atomicMax on inverted keys
// key = ~bits(max(d2,0)); identity 0 -> statically zero-init buffer; the
// reduce kernel re-zeroes slots after reading and its last block resets
// g_sum/g_done (stream-ordered for graph replay).
//
// Round-13: exact R9 main kernel (best measured: TC=512, Q=8, 2 blocks/SM),
// minimal 2-launch structure (main + self-resetting reduce).

#define NPTS    4096
#define NBATCH  16
#define THREADS 256
#define GRID    296                     // 2 blocks/SM x 148
#define TC      512                     // targets per chunk
#define NCHUNK  (NBATCH * 32 * 8)       // 4096 chunks (32 qstrips x 8 tchunks)
#define NQTOT   (2 * NBATCH * NPTS)     // 131072
#define BIGF    3.4e38f

#define P2_BLOCKS 128
#define P2_THREADS 256

typedef unsigned long long ull;

__device__ unsigned g_key[NQTOT];       // zero-init; [0:65536)=pred rows, rest=targ cols
__device__ float    g_sum;              // zero-init; reset by reduce's last block
__device__ unsigned g_done;             // zero-init; reset by reduce's last block

__device__ __forceinline__ ull dupf(float v) {
    ull r; asm("mov.b64 %0, {%1, %1};" : "=l"(r) : "f"(v)); return r;
}
__device__ __forceinline__ ull pk(float lo, float hi) {
    ull r; asm("mov.b64 %0, {%1, %2};" : "=l"(r) : "f"(lo), "f"(hi)); return r;
}
__device__ __forceinline__ unsigned mkkey(float d2) {
    return ~__float_as_uint(fmaxf(d2, 0.0f));
}

// ---- launch 1: pairwise mins ----
__global__ void __launch_bounds__(THREADS, 2)
cd_main_kernel(const float* __restrict__ pred, const float* __restrict__ targ) {
    __shared__ __align__(16) float4 sA[TC / 2];   // (y0_t0,y0_t1,y1_t0,y1_t1)
    __shared__ __align__(16) float4 sB[TC / 2];   // (y2_t0,y2_t1, h_t0, h_t1)
    __shared__ unsigned scol[TC];

    const int tid = threadIdx.x;
    const int tx  = tid & 15;
    const int ty  = tid >> 4;
    const int bid = blockIdx.x;

    scol[tid] = 0u;                     // identity (both halves)
    scol[tid + 256] = 0u;

    const int c0 = (int)(((long long)bid       * NCHUNK) / GRID);
    const int c1 = (int)(((long long)(bid + 1) * NCHUNK) / GRID);

    ull  m0[8], m1[8], m2[8], x2d[8];   // duplicated-lane query state
    float ralo[8], rahi[8];             // row-min accumulators
    int cur_strip = -1, cur_qbase = 0;

    for (int cid = c0; cid < c1; cid++) {
        const int b  = cid >> 8;        // 256 chunks per batch (32 qs x 8 tc)
        const int rr = cid & 255;
        const int qs = rr >> 3;
        const int tc = rr & 7;

        // ---- query strip management: flush 8 row mins, load 8 new queries ----
        const int strip = (b << 5) | qs;
        if (strip != cur_strip) {
            if (cur_strip >= 0) {
#pragma unroll
                for (int i = 0; i < 8; i++)
                    atomicMax(&g_key[cur_qbase + (ty << 3) + i],
                              mkkey(fminf(ralo[i], rahi[i])));
            }
            cur_strip = strip;
            cur_qbase = (b << 12) + (qs << 7);
            // 8 points = 24 floats = 6 x float4 (96B, 16B-aligned)
            const float4* __restrict__ qv =
                (const float4*)(pred + (size_t)(cur_qbase + (ty << 3)) * 3);
            float4 f[6];
#pragma unroll
            for (int i = 0; i < 6; i++) f[i] = qv[i];
            const float* q = (const float*)f;
#pragma unroll
            for (int i = 0; i < 8; i++) {
                const float x0 = q[i * 3 + 0];
                const float x1 = q[i * 3 + 1];
                const float x2 = q[i * 3 + 2];
                m0[i]  = dupf(-2.0f * x0);
                m1[i]  = dupf(-2.0f * x1);
                m2[i]  = dupf(-2.0f * x2);
                x2d[i] = dupf(x0 * x0 + x1 * x1 + x2 * x2);
                ralo[i] = BIGF; rahi[i] = BIGF;
            }
        }

        // ---- fill target tile: 256 threads x 2 targets, interleaved float4 ----
        {
            const float* __restrict__ bp =
                targ + (size_t)((b << 12) + (tc << 9) + tid * 2) * 3;
            const float a0 = bp[0], a1 = bp[1], a2 = bp[2];
            const float b0 = bp[3], b1 = bp[4], b2 = bp[5];
            sA[tid] = make_float4(a0, b0, a1, b1);
            sB[tid] = make_float4(a2, b2,
                                  a0 * a0 + a1 * a1 + a2 * a2,
                                  b0 * b0 + b1 * b1 + b2 * b2);
        }
        __syncthreads();    // A: tile + scol(identity) visible

        // ---- main: 16 target-pairs x 8 queries = 256 pairs/thread ----
#pragma unroll
        for (int k = 0; k < 16; k++) {
            const int pw = tx + (k << 4);
            const float4 ua = sA[pw];     // LDS.128
            const float4 ub = sB[pw];     // LDS.128
            const ull y0p = pk(ua.x, ua.y);
            const ull y1p = pk(ua.z, ua.w);
            const ull y2p = pk(ub.x, ub.y);
            const ull hp  = pk(ub.z, ub.w);
            float clo = BIGF, chi = BIGF;
#pragma unroll
            for (int q = 0; q < 8; q++) {
                ull s, w;
                asm("add.rn.f32x2 %0, %1, %2;"     : "=l"(s) : "l"(x2d[q]), "l"(hp));
                asm("fma.rn.f32x2 %0, %1, %2, %3;" : "=l"(w) : "l"(m2[q]), "l"(y2p), "l"(s));
                asm("fma.rn.f32x2 %0, %1, %2, %3;" : "=l"(w) : "l"(m1[q]), "l"(y1p), "l"(w));
                asm("fma.rn.f32x2 %0, %1, %2, %3;" : "=l"(w) : "l"(m0[q]), "l"(y0p), "l"(w));
                float wl, wh;
                asm("mov.b64 {%0, %1}, %2;" : "=f"(wl), "=f"(wh) : "l"(w));
                ralo[q] = fminf(ralo[q], wl);
                rahi[q] = fminf(rahi[q], wh);
                clo = fminf(clo, wl);
                chi = fminf(chi, wh);
            }
            // in-loop, return-less col merges
            const int w2 = (tx << 1) + (k << 5);
            atomicMax(&scol[w2],     mkkey(clo));
            atomicMax(&scol[w2 + 1], mkkey(chi));
        }
        __syncthreads();    // B: scol complete; tile reads done

        // ---- two global return-less atomicMax per thread; reset own slots ----
        const int gb = (NBATCH * NPTS) + (b << 12) + (tc << 9);
        atomicMax(&g_key[gb + tid],       scol[tid]);
        atomicMax(&g_key[gb + tid + 256], scol[tid + 256]);
        scol[tid] = 0u;
        scol[tid + 256] = 0u;
    }

    // final row flush
    if (cur_strip >= 0) {
#pragma unroll
        for (int i = 0; i < 8; i++)
            atomicMax(&g_key[cur_qbase + (ty << 3) + i],
                      mkkey(fminf(ralo[i], rahi[i])));
    }
}

// ---- launch 2: sqrt + mean; re-zeroes g_key; last block resets g_sum/g_done ----
__global__ void __launch_bounds__(P2_THREADS)
cd_reduce_kernel(float* __restrict__ out) {
    __shared__ float swsum[P2_THREADS / 32];
    const int tid = threadIdx.x;
    const int i = blockIdx.x * P2_THREADS + tid;     // 32768 threads, 1 uint4 each
    uint4* kp = reinterpret_cast<uint4*>(g_key);
    const uint4 kv = kp[i];
    float lsum = sqrtf(__uint_as_float(~kv.x)) + sqrtf(__uint_as_float(~kv.y))
               + sqrtf(__uint_as_float(~kv.z)) + sqrtf(__uint_as_float(~kv.w));
    kp[i] = make_uint4(0u, 0u, 0u, 0u);              // identity for next call
#pragma unroll
    for (int off = 16; off > 0; off >>= 1)
        lsum += __shfl_down_sync(0xFFFFFFFFu, lsum, off);
    const int lane = tid & 31;
    const int wid  = tid >> 5;
    if (lane == 0) swsum[wid] = lsum;
    __syncthreads();
    if (wid == 0) {
        float v = (lane < P2_THREADS / 32) ? swsum[lane] : 0.0f;
#pragma unroll
        for (int off = (P2_THREADS / 32) / 2; off > 0; off >>= 1)
            v += __shfl_down_sync(0xFFFFFFFFu, v, off);
        if (lane == 0) {
            atomicAdd(&g_sum, v);
            __threadfence();
            const unsigned rdone = atomicAdd(&g_done, 1u);
            if (rdone == P2_BLOCKS - 1) {
                out[0] = atomicAdd(&g_sum, 0.0f) * (1.0f / (float)(NBATCH * NPTS));
                g_sum = 0.0f;                        // reset for next replay
                g_done = 0u;
            }
        }
    }
}

extern "C" void kernel_launch(void* const* d_in, const int* in_sizes, int n_in,
                              void* d_out, int out_size) {
    const float* pred = (const float*)d_in[0];
    const float* targ = (const float*)d_in[1];
    float* out = (float*)d_out;
    cd_main_kernel<<<GRID, THREADS>>>(pred, targ);    // launch 1
    cd_reduce_kernel<<<P2_BLOCKS, P2_THREADS>>>(out); // launch 2
}